// round 5
// baseline (speedup 1.0000x reference)
#include <cuda_runtime.h>
#include <math.h>

#define N_NODES 100000
#define IN_DIM 256
#define HID 64
#define HEADS 3
#define FDIM 192          // HEADS*HID
#define NUM_CLASSES 10
#define NUM_GRAPHS 64
#define MAX_ET 1700000    // 1.6M edges + 100k self loops

// ---------------- static scratch (no allocations allowed) ----------------
__device__ float g_xl[(size_t)N_NODES * FDIM];
__device__ float g_xr[(size_t)N_NODES * FDIM];
__device__ int   g_src[MAX_ET];
__device__ int   g_deg[N_NODES];
__device__ int   g_tmp[N_NODES];
__device__ int   g_off[N_NODES + 1];
__device__ int   g_cur[N_NODES];
__device__ int   g_bsum[128];
__device__ float g_gsum[NUM_GRAPHS * FDIM];
__device__ int   g_gcnt[NUM_GRAPHS];

// ---------------- init ----------------
__global__ void k_zero() {
    int i = blockIdx.x * blockDim.x + threadIdx.x;
    if (i < N_NODES) g_deg[i] = 0;
    if (i < NUM_GRAPHS * FDIM) g_gsum[i] = 0.f;
    if (i < NUM_GRAPHS) g_gcnt[i] = 0;
}

// ---------------- fused GEMM: [xl | xr] = x @ [W_l | W_r] + [b_l | b_r] ----
// M=100000, K=256, Ncols=384. 128x128x8 tiles, 256 threads, 8x8 per thread.
__global__ __launch_bounds__(256) void k_gemm(
    const float* __restrict__ x,
    const float* __restrict__ Wl, const float* __restrict__ Wr,
    const float* __restrict__ bl, const float* __restrict__ br)
{
    __shared__ float As[8][132];
    __shared__ float Bs[8][128];
    const int tid = threadIdx.x;
    const int tx = tid & 15;          // 0..15 (cols)
    const int ty = tid >> 4;          // 0..15 (rows)
    const int row0 = blockIdx.y * 128;
    const int col0 = blockIdx.x * 128;

    float acc[8][8];
#pragma unroll
    for (int i = 0; i < 8; i++)
#pragma unroll
        for (int j = 0; j < 8; j++) acc[i][j] = 0.f;

    const int ar = tid >> 1;          // 0..127
    const int ac = (tid & 1) * 4;     // 0 or 4
    const int bk = tid >> 5;          // 0..7
    const int bn = (tid & 31) * 4;    // 0..124
    const int gcol = col0 + bn;
    const float* Wp;
    int wc;
    if (gcol < FDIM) { Wp = Wl; wc = gcol; } else { Wp = Wr; wc = gcol - FDIM; }

    for (int kt = 0; kt < IN_DIM; kt += 8) {
        // A tile (128x8), transposed into As[k][m]
        float4 av = make_float4(0.f, 0.f, 0.f, 0.f);
        int grow = row0 + ar;
        if (grow < N_NODES)
            av = *(const float4*)&x[(size_t)grow * IN_DIM + kt + ac];
        As[ac + 0][ar] = av.x;
        As[ac + 1][ar] = av.y;
        As[ac + 2][ar] = av.z;
        As[ac + 3][ar] = av.w;
        // B tile (8x128)
        float4 bv = *(const float4*)&Wp[(size_t)(kt + bk) * FDIM + wc];
        *(float4*)&Bs[bk][bn] = bv;
        __syncthreads();
#pragma unroll
        for (int k = 0; k < 8; k++) {
            float a[8], b[8];
#pragma unroll
            for (int i = 0; i < 8; i++) a[i] = As[k][ty * 8 + i];
#pragma unroll
            for (int j = 0; j < 8; j++) b[j] = Bs[k][tx * 8 + j];
#pragma unroll
            for (int i = 0; i < 8; i++)
#pragma unroll
                for (int j = 0; j < 8; j++) acc[i][j] += a[i] * b[j];
        }
        __syncthreads();
    }
#pragma unroll
    for (int i = 0; i < 8; i++) {
        int r = row0 + ty * 8 + i;
        if (r >= N_NODES) continue;
#pragma unroll
        for (int j = 0; j < 8; j++) {
            int c = col0 + tx * 8 + j;
            if (c < FDIM) g_xl[(size_t)r * FDIM + c] = acc[i][j] + bl[c];
            else          g_xr[(size_t)r * FDIM + (c - FDIM)] = acc[i][j] + br[c - FDIM];
        }
    }
}

// ---------------- CSR build (edge_index is INT32: jax x64 is disabled) ----
__global__ void k_deg(const int* __restrict__ eidx, int E, int ET) {
    int e = blockIdx.x * blockDim.x + threadIdx.x;
    if (e >= ET) return;
    int dst = (e < E) ? eidx[(size_t)E + e] : (e - E);
    if ((unsigned)dst >= N_NODES) return;   // defensive: wrong dtype -> rel_err, not trap
    atomicAdd(&g_deg[dst], 1);
}

__global__ void k_scan1() {   // 98 blocks x 1024: per-chunk inclusive scan
    __shared__ int s[1024];
    int tid = threadIdx.x;
    int i = blockIdx.x * 1024 + tid;
    int v = (i < N_NODES) ? g_deg[i] : 0;
    s[tid] = v;
    __syncthreads();
#pragma unroll
    for (int o = 1; o < 1024; o <<= 1) {
        int t = (tid >= o) ? s[tid - o] : 0;
        __syncthreads();
        s[tid] += t;
        __syncthreads();
    }
    if (i < N_NODES) g_tmp[i] = s[tid];
    if (tid == 1023) g_bsum[blockIdx.x] = s[1023];
}

__global__ void k_scan2(int nblk) {  // serial exclusive scan of block sums
    if (threadIdx.x == 0 && blockIdx.x == 0) {
        int run = 0;
        for (int b = 0; b < nblk; b++) { int t = g_bsum[b]; g_bsum[b] = run; run += t; }
    }
}

__global__ void k_scan3() {
    int i = blockIdx.x * blockDim.x + threadIdx.x;
    if (i >= N_NODES) return;
    int val = g_tmp[i] + g_bsum[i >> 10];
    g_off[i + 1] = val;
    g_cur[i] = val - g_deg[i];
    if (i == 0) g_off[0] = 0;
}

__global__ void k_fill(const int* __restrict__ eidx, int E, int ET) {
    int e = blockIdx.x * blockDim.x + threadIdx.x;
    if (e >= ET) return;
    int src, dst;
    if (e < E) { src = eidx[e]; dst = eidx[(size_t)E + e]; }
    else       { src = e - E; dst = e - E; }
    if ((unsigned)dst >= N_NODES || (unsigned)src >= N_NODES) return;  // defensive
    int p = atomicAdd(&g_cur[dst], 1);
    if ((unsigned)p < MAX_ET) g_src[p] = src;
}

// ---------------- warp-per-node GATv2 with online softmax ----------------
__global__ __launch_bounds__(256) void k_attn(
    const float* __restrict__ att, const float* __restrict__ bias,
    float* __restrict__ out_fc, float* __restrict__ out_pre)
{
    int warp = (blockIdx.x * blockDim.x + threadIdx.x) >> 5;
    int lane = threadIdx.x & 31;
    if (warp >= N_NODES) return;
    const int i = warp;

    float xrv[6], attv[6];
#pragma unroll
    for (int k = 0; k < 6; k++) {
        int c = lane + 32 * k;
        xrv[k] = g_xr[(size_t)i * FDIM + c];
        attv[k] = att[c];   // att flattened [3,64] == channel index
    }
    int beg = g_off[i], end = g_off[i + 1];

    float m0 = -1e30f, m1 = -1e30f, m2 = -1e30f;
    float d0 = 0.f, d1 = 0.f, d2 = 0.f;
    float acc[6] = {0.f, 0.f, 0.f, 0.f, 0.f, 0.f};

    for (int e = beg; e < end; e++) {
        int s = g_src[e];
        const float* xl = &g_xl[(size_t)s * FDIM];
        float xlv[6];
        float p0 = 0.f, p1 = 0.f, p2 = 0.f;
#pragma unroll
        for (int k = 0; k < 6; k++) {
            float v = xl[lane + 32 * k];
            xlv[k] = v;
            float t = v + xrv[k];
            t = t > 0.f ? t : 0.2f * t;
            float pe = t * attv[k];
            if (k < 2) p0 += pe; else if (k < 4) p1 += pe; else p2 += pe;
        }
#pragma unroll
        for (int o = 16; o; o >>= 1) {
            p0 += __shfl_xor_sync(0xffffffffu, p0, o);
            p1 += __shfl_xor_sync(0xffffffffu, p1, o);
            p2 += __shfl_xor_sync(0xffffffffu, p2, o);
        }
        float s0, w0, s1, w1, s2, w2;
        if (p0 > m0) { s0 = __expf(m0 - p0); m0 = p0; d0 = d0 * s0 + 1.f; w0 = 1.f; }
        else         { w0 = __expf(p0 - m0); d0 += w0; s0 = 1.f; }
        if (p1 > m1) { s1 = __expf(m1 - p1); m1 = p1; d1 = d1 * s1 + 1.f; w1 = 1.f; }
        else         { w1 = __expf(p1 - m1); d1 += w1; s1 = 1.f; }
        if (p2 > m2) { s2 = __expf(m2 - p2); m2 = p2; d2 = d2 * s2 + 1.f; w2 = 1.f; }
        else         { w2 = __expf(p2 - m2); d2 += w2; s2 = 1.f; }
        acc[0] = acc[0] * s0 + w0 * xlv[0];
        acc[1] = acc[1] * s0 + w0 * xlv[1];
        acc[2] = acc[2] * s1 + w1 * xlv[2];
        acc[3] = acc[3] * s1 + w1 * xlv[3];
        acc[4] = acc[4] * s2 + w2 * xlv[4];
        acc[5] = acc[5] * s2 + w2 * xlv[5];
    }
    float i0 = 1.f / d0, i1 = 1.f / d1, i2 = 1.f / d2;
#pragma unroll
    for (int k = 0; k < 6; k++) {
        float inv = (k < 2) ? i0 : (k < 4) ? i1 : i2;
        int c = lane + 32 * k;
        float o = acc[k] * inv + bias[c];
        out_fc[(size_t)i * FDIM + c] = o;
        out_pre[(size_t)i * FDIM + c] = o > 0.f ? o : 0.01f * o;
    }
}

// ---------------- pooling (batch is sorted int32 -> register accumulate) --
__global__ __launch_bounds__(192) void k_pool(
    const int* __restrict__ batch, const float* __restrict__ pre)
{
    const int NPB = 128;
    int n0 = blockIdx.x * NPB;
    int t = threadIdx.x;     // channel 0..191
    int nend = n0 + NPB; if (nend > N_NODES) nend = N_NODES;
    float a = 0.f; int cnt = 0; int cur = -1;
    for (int n = n0; n < nend; n++) {
        int g = __ldg(&batch[n]);
        if ((unsigned)g >= NUM_GRAPHS) continue;  // defensive
        if (g != cur) {
            if (cur >= 0) {
                atomicAdd(&g_gsum[cur * FDIM + t], a);
                if (t == 0) atomicAdd(&g_gcnt[cur], cnt);
            }
            a = 0.f; cnt = 0; cur = g;
        }
        a += pre[(size_t)n * FDIM + t];
        cnt++;
    }
    if (cur >= 0) {
        atomicAdd(&g_gsum[cur * FDIM + t], a);
        if (t == 0) atomicAdd(&g_gcnt[cur], cnt);
    }
}

// ---------------- post_pool + classifier ---------------------------------
__global__ __launch_bounds__(192) void k_final(
    const float* __restrict__ Wc, const float* __restrict__ bc,
    float* __restrict__ out_logits, float* __restrict__ out_post)
{
    int g = blockIdx.x;
    int t = threadIdx.x;
    __shared__ float sp[FDIM];
    float cnt = (float)g_gcnt[g];
    cnt = fmaxf(cnt, 1.f);
    float v = g_gsum[g * FDIM + t] / cnt;
    out_post[g * FDIM + t] = v;
    sp[t] = v;
    __syncthreads();
    if (t < NUM_CLASSES) {
        float s = bc[t];
        for (int k = 0; k < FDIM; k++) s += sp[k] * Wc[k * NUM_CLASSES + t];
        out_logits[g * NUM_CLASSES + t] = s;
    }
}

// ---------------- launch ----------------
extern "C" void kernel_launch(void* const* d_in, const int* in_sizes, int n_in,
                              void* d_out, int out_size)
{
    const float* x     = (const float*)d_in[0];
    const int*   eidx  = (const int*)d_in[1];    // int32 (jax x64 disabled)
    const int*   batch = (const int*)d_in[2];    // int32
    const float* Wl    = (const float*)d_in[3];
    const float* bl    = (const float*)d_in[4];
    const float* Wr    = (const float*)d_in[5];
    const float* br    = (const float*)d_in[6];
    const float* att   = (const float*)d_in[7];
    const float* bias  = (const float*)d_in[8];
    const float* Wc    = (const float*)d_in[9];
    const float* bc    = (const float*)d_in[10];
    float* out = (float*)d_out;

    int E = in_sizes[1] / 2;
    int ET = E + N_NODES;

    // output layout: (logits, pre_pool, post_pool, first_conv) flattened
    float* out_logits = out;
    float* out_pre    = out + NUM_GRAPHS * NUM_CLASSES;
    float* out_post   = out_pre + (size_t)N_NODES * FDIM;
    float* out_fc     = out_post + NUM_GRAPHS * FDIM;

    k_zero<<<(N_NODES + 255) / 256, 256>>>();
    k_gemm<<<dim3(3, (N_NODES + 127) / 128), 256>>>(x, Wl, Wr, bl, br);
    k_deg<<<(ET + 255) / 256, 256>>>(eidx, E, ET);
    int nblk = (N_NODES + 1023) / 1024;
    k_scan1<<<nblk, 1024>>>();
    k_scan2<<<1, 32>>>(nblk);
    k_scan3<<<(N_NODES + 255) / 256, 256>>>();
    k_fill<<<(ET + 255) / 256, 256>>>(eidx, E, ET);
    k_attn<<<(N_NODES * 32 + 255) / 256, 256>>>(att, bias, out_fc, out_pre);
    k_pool<<<(N_NODES + 127) / 128, 192>>>(batch, out_pre);
    k_final<<<NUM_GRAPHS, 192>>>(Wc, bc, out_logits, out_post);
}